// round 1
// baseline (speedup 1.0000x reference)
#include <cuda_runtime.h>
#include <math.h>

#define TABLE_SIZE   (1u << 19)
#define HASH_MASK    (TABLE_SIZE - 1u)
#define PRIME1       2654435761u

#define PTS      64      // points per block
#define NTHREADS 256
#define XSTRIDE  36      // 34 features padded to 36 (16B-aligned rows)
#define HSTRIDE  68      // 64 points padded (16B-aligned rows, bank-spread)
#define KCHUNK   32

// floor(16 * 2^(l/3)) computed in double precision
__device__ __constant__ float RES_TAB[16] = {
    16.f, 20.f, 25.f, 32.f, 40.f, 50.f, 64.f, 80.f,
    101.f, 128.f, 161.f, 203.f, 256.f, 322.f, 406.f, 512.f
};

// Dynamic smem layout (floats):
//   xenc : [PTS][XSTRIDE]      = 2304
//   ha   : [256][HSTRIDE]      = 17408
//   hb   : [256][HSTRIDE]      = 17408
//   wt   : [KCHUNK][256]       = 8192
// total 45312 floats = 181248 bytes
#define SMEM_FLOATS (PTS*XSTRIDE + 2*256*HSTRIDE + KCHUNK*256)

extern "C" __global__ void __launch_bounds__(NTHREADS, 1)
ngp_fused_kernel(const float* __restrict__ coords,
                 const float* __restrict__ emb,
                 const float* __restrict__ W0, const float* __restrict__ b0,
                 const float* __restrict__ W1, const float* __restrict__ b1,
                 const float* __restrict__ W2, const float* __restrict__ b2,
                 float* __restrict__ out, int npts)
{
    extern __shared__ float smem[];
    float* xenc = smem;
    float* ha   = smem + PTS * XSTRIDE;
    float* hb   = ha + 256 * HSTRIDE;
    float* wt   = hb + 256 * HSTRIDE;

    const int t  = threadIdx.x;
    const int p0 = blockIdx.x * PTS;

    // ---------------- encode: hash-grid features -> xenc[p][0..35] ----------
    {
        const int p  = t >> 2;     // point within block
        const int g  = t & 3;      // level group (4 levels each)
        const int gp = p0 + p;

        float2 c = make_float2(0.f, 0.f);
        if (gp < npts) c = ((const float2*)coords)[gp];
        const float x = fminf(fmaxf(c.x, -1.f), 1.f);
        const float y = fminf(fmaxf(c.y, -1.f), 1.f);

        if (g == 0) { xenc[p*XSTRIDE + 0] = x; xenc[p*XSTRIDE + 1] = y; }
        if (g == 3) { xenc[p*XSTRIDE + 34] = 0.f; xenc[p*XSTRIDE + 35] = 0.f; }

        #pragma unroll
        for (int li = 0; li < 4; li++) {
            const int l = g * 4 + li;
            const float res  = RES_TAB[l];
            const float grid = 2.0f / res;
            const float blxf = floorf((x + 1.0f) / grid);
            const float blyf = floorf((y + 1.0f) / grid);
            // w = (xy - (bl*grid + box_min)) / grid
            const float wx = (x - (blxf * grid - 1.0f)) / grid;
            const float wy = (y - (blyf * grid - 1.0f)) / grid;

            const unsigned bx = (unsigned)(int)blxf;
            const unsigned by = (unsigned)(int)blyf;
            const unsigned hx0 = bx;
            const unsigned hx1 = bx + 1u;
            const unsigned hy0 = by * PRIME1;
            const unsigned hy1 = (by + 1u) * PRIME1;

            const float2* tab = (const float2*)emb + (size_t)l * TABLE_SIZE;
            const float2 e00 = tab[(hx0 ^ hy0) & HASH_MASK];
            const float2 e01 = tab[(hx0 ^ hy1) & HASH_MASK];
            const float2 e10 = tab[(hx1 ^ hy0) & HASH_MASK];
            const float2 e11 = tab[(hx1 ^ hy1) & HASH_MASK];

            const float omx = 1.0f - wx, omy = 1.0f - wy;
            const float f0 = (e00.x*omx + e10.x*wx)*omy + (e01.x*omx + e11.x*wx)*wy;
            const float f1 = (e00.y*omx + e10.y*wx)*omy + (e01.y*omx + e11.y*wx)*wy;
            xenc[p*XSTRIDE + 2 + 2*l]     = f0;
            xenc[p*XSTRIDE + 2 + 2*l + 1] = f1;
        }
    }
    __syncthreads();

    // ---------------- layer 0: ha[n][p] = relu(b0[n] + x[p,:] @ W0[:,n]) ----
    {
        const int n = t;
        float w0r[36];
        #pragma unroll
        for (int k = 0; k < 34; k++) w0r[k] = W0[k * 256 + n];
        w0r[34] = 0.f; w0r[35] = 0.f;
        const float bias = b0[n];

        for (int p = 0; p < PTS; p++) {
            const float4* xr = (const float4*)(xenc + p * XSTRIDE);
            float a = bias;
            #pragma unroll
            for (int k4 = 0; k4 < 9; k4++) {
                const float4 v = xr[k4];
                a += v.x * w0r[4*k4+0];
                a += v.y * w0r[4*k4+1];
                a += v.z * w0r[4*k4+2];
                a += v.w * w0r[4*k4+3];
            }
            ha[n * HSTRIDE + p] = fmaxf(a, 0.f);
        }
    }
    __syncthreads();

    // ---------------- layer 1: hb[n][p] = relu(b1[n] + ha[:,p] @ W1[:,n]) ---
    {
        const int n = t;
        const float bias = b1[n];
        float acc[PTS];
        #pragma unroll
        for (int p = 0; p < PTS; p++) acc[p] = 0.f;

        for (int kt = 0; kt < 256; kt += KCHUNK) {
            __syncthreads();
            // stage W1[kt..kt+31][:] into wt (coalesced)
            #pragma unroll
            for (int r = 0; r < KCHUNK; r++)
                wt[r * 256 + t] = W1[(kt + r) * 256 + t];
            __syncthreads();

            for (int r = 0; r < KCHUNK; r++) {
                const float w = wt[r * 256 + n];
                const float4* hr = (const float4*)(ha + (kt + r) * HSTRIDE);
                #pragma unroll
                for (int p4 = 0; p4 < PTS / 4; p4++) {
                    const float4 h = hr[p4];
                    acc[4*p4+0] += h.x * w;
                    acc[4*p4+1] += h.y * w;
                    acc[4*p4+2] += h.z * w;
                    acc[4*p4+3] += h.w * w;
                }
            }
        }
        #pragma unroll
        for (int p = 0; p < PTS; p++)
            hb[n * HSTRIDE + p] = fmaxf(acc[p] + bias, 0.f);
    }
    __syncthreads();

    // ---------------- layer 2 + sigmoid: out[p][c] ---------------------------
    // stage W2 (256x3 = 768 floats) into wt
    wt[t]       = W2[t];
    wt[256 + t] = W2[256 + t];
    wt[512 + t] = W2[512 + t];
    __syncthreads();

    if (t < PTS * 3) {
        const int p = t / 3;
        const int c = t % 3;
        float a0 = b2[c], a1 = 0.f;
        #pragma unroll 8
        for (int k = 0; k < 256; k += 2) {
            a0 += hb[k * HSTRIDE + p]       * wt[k * 3 + c];
            a1 += hb[(k + 1) * HSTRIDE + p] * wt[(k + 1) * 3 + c];
        }
        const float a = a0 + a1;
        const float s = 1.0f / (1.0f + expf(-a));
        const int gp = p0 + p;
        if (gp < npts) out[gp * 3 + c] = s;
    }
}

extern "C" void kernel_launch(void* const* d_in, const int* in_sizes, int n_in,
                              void* d_out, int out_size)
{
    const float* coords = (const float*)d_in[0];
    const float* emb    = (const float*)d_in[1];
    const float* W0     = (const float*)d_in[2];
    const float* b0     = (const float*)d_in[3];
    const float* W1     = (const float*)d_in[4];
    const float* b1     = (const float*)d_in[5];
    const float* W2     = (const float*)d_in[6];
    const float* b2     = (const float*)d_in[7];
    float* out          = (float*)d_out;

    const int npts = in_sizes[0] / 2;
    const int smem_bytes = SMEM_FLOATS * (int)sizeof(float);

    cudaFuncSetAttribute(ngp_fused_kernel,
                         cudaFuncAttributeMaxDynamicSharedMemorySize, smem_bytes);

    const int nblocks = (npts + PTS - 1) / PTS;
    ngp_fused_kernel<<<nblocks, NTHREADS, smem_bytes>>>(
        coords, emb, W0, b0, W1, b1, W2, b2, out, npts);
}

// round 3
// speedup vs baseline: 7.4823x; 7.4823x over previous
#include <cuda_runtime.h>
#include <cuda_bf16.h>
#include <cstdint>
#include <math.h>

#define TABLE_SIZE (1u << 19)
#define HASH_MASK  (TABLE_SIZE - 1u)
#define PRIME1     2654435761u
#define NTH        256
#define PTS        64

// floor(16 * 2^(l/3)) — validated vs reference in R1 (rel_err 2e-7)
__device__ __constant__ float RES_TAB[16] = {
    16.f, 20.f, 25.f, 32.f, 40.f, 50.f, 64.f, 80.f,
    101.f, 128.f, 161.f, 203.f, 256.f, 322.f, 406.f, 512.f
};

// ---- smem layout (bytes). Row strides: big = 528B (256k + 8 pad bf16),
// small = 112B (48k + 8 pad bf16). Both give conflict-free ldmatrix. ----
#define WS_BIG   528
#define WS_SMALL 112
#define W1T_OFF  0                        // [256 n][264] bf16 : 135168
#define W0T_OFF  135168                   // [256 n][56]  bf16 : 28672
#define W2T_OFF  163840                   // [16 n][264]  bf16 : 8448
#define X_OFF    172288                   // [64 m][56]   bf16 : 7168
#define ACT_OFF  179456                   // [64 m][264]  bf16 : 33792
#define B0_OFF   213248                   // 256 f32
#define B1_OFF   214272                   // 256 f32
#define B2_OFF   215296                   // 4 f32
#define OUTB_OFF 215312                   // 192 f32
#define SMEM_BYTES 216080

__device__ __forceinline__ uint32_t smem_u32(const void* p) {
    uint32_t a;
    asm("{ .reg .u64 t; cvta.to.shared.u64 t, %1; cvt.u32.u64 %0, t; }" : "=r"(a) : "l"(p));
    return a;
}
__device__ __forceinline__ void ldm_x4(uint32_t* r, uint32_t addr) {
    asm volatile("ldmatrix.sync.aligned.m8n8.x4.shared.b16 {%0,%1,%2,%3}, [%4];"
        : "=r"(r[0]), "=r"(r[1]), "=r"(r[2]), "=r"(r[3]) : "r"(addr));
}
__device__ __forceinline__ void ldm_x2(uint32_t* r, uint32_t addr) {
    asm volatile("ldmatrix.sync.aligned.m8n8.x2.shared.b16 {%0,%1}, [%2];"
        : "=r"(r[0]), "=r"(r[1]) : "r"(addr));
}
__device__ __forceinline__ void mma_bf16(float* d, const uint32_t* a, const uint32_t* b) {
    asm volatile("mma.sync.aligned.m16n8k16.row.col.f32.bf16.bf16.f32 "
        "{%0,%1,%2,%3}, {%4,%5,%6,%7}, {%8,%9}, {%0,%1,%2,%3};"
        : "+f"(d[0]), "+f"(d[1]), "+f"(d[2]), "+f"(d[3])
        : "r"(a[0]), "r"(a[1]), "r"(a[2]), "r"(a[3]), "r"(b[0]), "r"(b[1]));
}
__device__ __forceinline__ uint32_t packbf(float lo, float hi) {
    __nv_bfloat162 h = __floats2bfloat162_rn(lo, hi);
    return *reinterpret_cast<uint32_t*>(&h);
}

// D[64 x 256-slice] += X[64 x 16*KT] @ Wt^T, warp handles n-cols [nbase, nbase+32)
template<int KT>
__device__ __forceinline__ void gemm_tile(uint32_t xlane, int xs, uint32_t wlane,
                                          float acc[4][4][4]) {
    #pragma unroll
    for (int ks = 0; ks < KT; ks++) {
        uint32_t a[4][4], b[4][2];
        #pragma unroll
        for (int i = 0; i < 4; i++) ldm_x4(a[i], xlane + i * 16 * xs + ks * 32);
        #pragma unroll
        for (int j = 0; j < 4; j++) ldm_x2(b[j], wlane + j * 8 * WS_BIG + ks * 32);
        #pragma unroll
        for (int i = 0; i < 4; i++)
            #pragma unroll
            for (int j = 0; j < 4; j++) mma_bf16(acc[i][j], a[i], b[j]);
    }
}

// relu(acc + bias) -> bf16 pairs into ACT (row = point, col = neuron index)
__device__ __forceinline__ void epi_store(float acc[4][4][4], char* smem,
                                          const float* __restrict__ bias,
                                          int nbase, int lane) {
    #pragma unroll
    for (int i = 0; i < 4; i++) {
        const int r0 = i * 16 + (lane >> 2);
        #pragma unroll
        for (int j = 0; j < 4; j++) {
            const int c = nbase + j * 8 + (lane & 3) * 2;
            const float bx = bias[c], by = bias[c + 1];
            const uint32_t lo = packbf(fmaxf(acc[i][j][0] + bx, 0.f),
                                       fmaxf(acc[i][j][1] + by, 0.f));
            const uint32_t hi = packbf(fmaxf(acc[i][j][2] + bx, 0.f),
                                       fmaxf(acc[i][j][3] + by, 0.f));
            *(uint32_t*)(smem + ACT_OFF + r0 * WS_BIG + c * 2)       = lo;
            *(uint32_t*)(smem + ACT_OFF + (r0 + 8) * WS_BIG + c * 2) = hi;
        }
    }
}

extern "C" __global__ void __launch_bounds__(NTH, 1)
ngp_hmma_kernel(const float* __restrict__ coords,
                const float* __restrict__ emb,
                const float* __restrict__ W0, const float* __restrict__ b0,
                const float* __restrict__ W1, const float* __restrict__ b1,
                const float* __restrict__ W2, const float* __restrict__ b2,
                float* __restrict__ out, int npts)
{
    extern __shared__ char smem[];
    const uint32_t sb = smem_u32(smem);
    const int t = threadIdx.x;
    const int lane = t & 31;
    const int w = t >> 5;

    // ---- one-time weight staging ----
    for (int i = t; i < 7168; i += NTH) ((uint32_t*)(smem + W0T_OFF))[i] = 0;
    for (int i = t; i < 2112; i += NTH) ((uint32_t*)(smem + W2T_OFF))[i] = 0;
    __syncthreads();
    for (int i = t; i < 256 * 256; i += NTH) {
        const int k = i >> 8, n = i & 255;
        *(__nv_bfloat16*)(smem + W1T_OFF + n * WS_BIG + k * 2) = __float2bfloat16(W1[i]);
    }
    for (int i = t; i < 34 * 256; i += NTH) {
        const int k = i >> 8, n = i & 255;
        *(__nv_bfloat16*)(smem + W0T_OFF + n * WS_SMALL + k * 2) = __float2bfloat16(W0[i]);
    }
    for (int i = t; i < 256 * 3; i += NTH) {
        const int k = i / 3, n = i - 3 * k;
        *(__nv_bfloat16*)(smem + W2T_OFF + n * WS_BIG + k * 2) = __float2bfloat16(W2[i]);
    }
    float* b0s = (float*)(smem + B0_OFF);
    float* b1s = (float*)(smem + B1_OFF);
    float* b2s = (float*)(smem + B2_OFF);
    float* outbuf = (float*)(smem + OUTB_OFF);
    for (int i = t; i < 256; i += NTH) { b0s[i] = b0[i]; b1s[i] = b1[i]; }
    if (t < 3) b2s[t] = b2[t];
    __syncthreads();

    // ldmatrix lane address components
    const int arow  = (lane & 7) + ((lane >> 3) & 1) * 8;   // A: row within m16 tile
    const int akoff = (lane >> 4) * 8;                      // A: k offset
    const int brow  = lane & 7;                             // B: row within n8 tile
    const int bkoff = ((lane >> 3) & 1) * 8;                // B: k offset
    const int nbase = w * 32;

    const uint32_t xlane0 = sb + X_OFF   + arow * WS_SMALL + akoff * 2;
    const uint32_t alane  = sb + ACT_OFF + arow * WS_BIG   + akoff * 2;
    const uint32_t w0lane = sb + W0T_OFF + (nbase + brow) * WS_SMALL + bkoff * 2;
    const uint32_t w1lane = sb + W1T_OFF + (nbase + brow) * WS_BIG   + bkoff * 2;
    const uint32_t w2lane = sb + W2T_OFF + ((w >> 2) * 8 + brow) * WS_BIG + bkoff * 2;
    const uint32_t a2lane = alane + (w & 3) * 16 * WS_BIG;  // layer2 A (m-tile = w&3)

    const int ntiles = (npts + PTS - 1) / PTS;

    for (int tile = blockIdx.x; tile < ntiles; tile += gridDim.x) {
        // ================= encode: 4 threads/point, 4 levels each =================
        {
            const int p = t >> 2;
            const int g = t & 3;
            const int gp = tile * PTS + p;
            float2 c = make_float2(0.f, 0.f);
            if (gp < npts) c = ((const float2*)coords)[gp];
            const float x = fminf(fmaxf(c.x, -1.f), 1.f);
            const float y = fminf(fmaxf(c.y, -1.f), 1.f);
            char* xrow = smem + X_OFF + p * WS_SMALL;

            if (g == 0) *(uint32_t*)xrow = packbf(x, y);
            if (g == 3) {   // zero k = 34..47
                #pragma unroll
                for (int z = 0; z < 7; z++) *(uint32_t*)(xrow + 68 + 4 * z) = 0;
            }
            #pragma unroll
            for (int li = 0; li < 4; li++) {
                const int l = g * 4 + li;
                const float res  = RES_TAB[l];
                const float grid = 2.0f / res;
                const float fx = floorf((x + 1.0f) / grid);
                const float fy = floorf((y + 1.0f) / grid);
                const float wx = (x - (fx * grid - 1.0f)) / grid;
                const float wy = (y - (fy * grid - 1.0f)) / grid;
                const unsigned bx = (unsigned)(int)fx;
                const unsigned by = (unsigned)(int)fy;
                const unsigned hy0 = by * PRIME1;
                const unsigned hy1 = (by + 1u) * PRIME1;
                const float2* tabl = (const float2*)emb + (size_t)l * TABLE_SIZE;
                const float2 e00 = tabl[(bx ^ hy0) & HASH_MASK];
                const float2 e01 = tabl[(bx ^ hy1) & HASH_MASK];
                const float2 e10 = tabl[((bx + 1u) ^ hy0) & HASH_MASK];
                const float2 e11 = tabl[((bx + 1u) ^ hy1) & HASH_MASK];
                const float omx = 1.f - wx, omy = 1.f - wy;
                const float f0 = (e00.x * omx + e10.x * wx) * omy + (e01.x * omx + e11.x * wx) * wy;
                const float f1 = (e00.y * omx + e10.y * wx) * omy + (e01.y * omx + e11.y * wx) * wy;
                *(uint32_t*)(xrow + (2 + 2 * l) * 2) = packbf(f0, f1);
            }
        }
        __syncthreads();

        // ================= layer 0: [64,48] @ W0t -> relu -> ACT =================
        {
            float acc[4][4][4];
            #pragma unroll
            for (int i = 0; i < 4; i++)
                #pragma unroll
                for (int j = 0; j < 4; j++)
                    #pragma unroll
                    for (int q = 0; q < 4; q++) acc[i][j][q] = 0.f;
            // K=48 (3 k-steps), B stride is WS_SMALL here: inline variant
            #pragma unroll
            for (int ks = 0; ks < 3; ks++) {
                uint32_t a[4][4], b[4][2];
                #pragma unroll
                for (int i = 0; i < 4; i++) ldm_x4(a[i], xlane0 + i * 16 * WS_SMALL + ks * 32);
                #pragma unroll
                for (int j = 0; j < 4; j++) ldm_x2(b[j], w0lane + j * 8 * WS_SMALL + ks * 32);
                #pragma unroll
                for (int i = 0; i < 4; i++)
                    #pragma unroll
                    for (int j = 0; j < 4; j++) mma_bf16(acc[i][j], a[i], b[j]);
            }
            epi_store(acc, smem, b0s, nbase, lane);   // X -> ACT, no WAR hazard
        }
        __syncthreads();

        // ================= layer 1: [64,256] @ W1t -> relu -> ACT ================
        {
            float acc[4][4][4];
            #pragma unroll
            for (int i = 0; i < 4; i++)
                #pragma unroll
                for (int j = 0; j < 4; j++)
                    #pragma unroll
                    for (int q = 0; q < 4; q++) acc[i][j][q] = 0.f;
            gemm_tile<16>(alane, WS_BIG, w1lane, acc);
            __syncthreads();                     // all reads of ACT done before overwrite
            epi_store(acc, smem, b1s, nbase, lane);
        }
        __syncthreads();

        // ================= layer 2 + sigmoid =====================================
        {
            float acc2[4] = {0.f, 0.f, 0.f, 0.f};
            #pragma unroll 4
            for (int ks = 0; ks < 16; ks++) {
                uint32_t a[4], b[2];
                ldm_x4(a, a2lane + ks * 32);
                ldm_x2(b, w2lane + ks * 32);
                mma_bf16(acc2, a, b);
            }
            if (w < 4) {   // these warps own n-cols 0..7; only cols 0..2 are real
                const int r = (w & 3) * 16 + (lane >> 2);
                const int c = (lane & 3) * 2;
                if (c < 3) {
                    outbuf[r * 3 + c]       = 1.f / (1.f + expf(-(acc2[0] + b2s[c])));
                    outbuf[(r + 8) * 3 + c] = 1.f / (1.f + expf(-(acc2[2] + b2s[c])));
                }
                if (c + 1 < 3) {
                    outbuf[r * 3 + c + 1]       = 1.f / (1.f + expf(-(acc2[1] + b2s[c + 1])));
                    outbuf[(r + 8) * 3 + c + 1] = 1.f / (1.f + expf(-(acc2[3] + b2s[c + 1])));
                }
            }
        }
        __syncthreads();

        if (t < PTS * 3) {
            const long gi = (long)tile * (PTS * 3) + t;
            if (gi < (long)npts * 3) out[gi] = outbuf[t];
        }
        __syncthreads();
    }
}

extern "C" void kernel_launch(void* const* d_in, const int* in_sizes, int n_in,
                              void* d_out, int out_size)
{
    const float* coords = (const float*)d_in[0];
    const float* emb    = (const float*)d_in[1];
    const float* W0     = (const float*)d_in[2];
    const float* b0     = (const float*)d_in[3];
    const float* W1     = (const float*)d_in[4];
    const float* b1     = (const float*)d_in[5];
    const float* W2     = (const float*)d_in[6];
    const float* b2     = (const float*)d_in[7];
    float* out          = (float*)d_out;

    const int npts = in_sizes[0] / 2;

    int dev = 0, nsm = 148;
    cudaGetDevice(&dev);
    cudaDeviceGetAttribute(&nsm, cudaDevAttrMultiProcessorCount, dev);

    cudaFuncSetAttribute(ngp_hmma_kernel,
                         cudaFuncAttributeMaxDynamicSharedMemorySize, SMEM_BYTES);

    ngp_hmma_kernel<<<nsm, NTH, SMEM_BYTES>>>(coords, emb, W0, b0, W1, b1, W2, b2, out, npts);
}

// round 4
// speedup vs baseline: 10.2897x; 1.3752x over previous
#include <cuda_runtime.h>
#include <cuda_bf16.h>
#include <cstdint>
#include <math.h>

#define TABLE_SIZE (1u << 19)
#define HASH_MASK  (TABLE_SIZE - 1u)
#define PRIME1     2654435761u
#define NTH        384          // 256 consumer + 128 producer
#define NCONS      256
#define PTS        64

// floor(16 * 2^(l/3)) — validated vs reference (rel_err 2e-7 in fp32 run)
__device__ __constant__ float RES_TAB[16] = {
    16.f, 20.f, 25.f, 32.f, 40.f, 50.f, 64.f, 80.f,
    101.f, 128.f, 161.f, 203.f, 256.f, 322.f, 406.f, 512.f
};

// ---- smem layout (bytes). Row strides: big = 528B, small = 112B ----
#define WS_BIG   528
#define WS_SMALL 112
#define W1T_OFF  0               // [256 n][264] bf16 : 135168
#define W0T_OFF  135168          // [256 n][56]  bf16 : 28672
#define W2T_OFF  163840          // [16 n][264]  bf16 : 8448
#define X_OFF    172288          // 2 x [64 m][56] bf16 : 14336
#define X_BUFSZ  7168
#define ACT_OFF  186624          // [64 m][264] bf16 : 33792
#define B0_OFF   220416          // 256 f32
#define B1_OFF   221440          // 256 f32
#define B2_OFF   222464          // 4 f32
#define OUTB_OFF 222480          // 192 f32
#define SMEM_BYTES 223248

// named barriers
#define BAR_FULL0  1
#define BAR_FULL1  2
#define BAR_EMPTY0 3
#define BAR_EMPTY1 4
#define BAR_CONS   5

__device__ __forceinline__ void bar_sync(int id, int cnt) {
    asm volatile("bar.sync %0, %1;" :: "r"(id), "r"(cnt) : "memory");
}
__device__ __forceinline__ void bar_arrive(int id, int cnt) {
    asm volatile("bar.arrive %0, %1;" :: "r"(id), "r"(cnt) : "memory");
}
__device__ __forceinline__ uint32_t smem_u32(const void* p) {
    uint32_t a;
    asm("{ .reg .u64 t; cvta.to.shared.u64 t, %1; cvt.u32.u64 %0, t; }" : "=r"(a) : "l"(p));
    return a;
}
__device__ __forceinline__ void ldm_x4(uint32_t* r, uint32_t addr) {
    asm volatile("ldmatrix.sync.aligned.m8n8.x4.shared.b16 {%0,%1,%2,%3}, [%4];"
        : "=r"(r[0]), "=r"(r[1]), "=r"(r[2]), "=r"(r[3]) : "r"(addr));
}
__device__ __forceinline__ void ldm_x2(uint32_t* r, uint32_t addr) {
    asm volatile("ldmatrix.sync.aligned.m8n8.x2.shared.b16 {%0,%1}, [%2];"
        : "=r"(r[0]), "=r"(r[1]) : "r"(addr));
}
__device__ __forceinline__ void mma_bf16(float* d, const uint32_t* a, const uint32_t* b) {
    asm volatile("mma.sync.aligned.m16n8k16.row.col.f32.bf16.bf16.f32 "
        "{%0,%1,%2,%3}, {%4,%5,%6,%7}, {%8,%9}, {%0,%1,%2,%3};"
        : "+f"(d[0]), "+f"(d[1]), "+f"(d[2]), "+f"(d[3])
        : "r"(a[0]), "r"(a[1]), "r"(a[2]), "r"(a[3]), "r"(b[0]), "r"(b[1]));
}
__device__ __forceinline__ uint32_t packbf(float lo, float hi) {
    __nv_bfloat162 h = __floats2bfloat162_rn(lo, hi);
    return *reinterpret_cast<uint32_t*>(&h);
}

// relu(acc + bias) -> bf16 pairs into ACT (row = point, col = neuron)
__device__ __forceinline__ void epi_store(float acc[4][4][4], char* smem,
                                          const float* __restrict__ bias,
                                          int nbase, int lane) {
    #pragma unroll
    for (int i = 0; i < 4; i++) {
        const int r0 = i * 16 + (lane >> 2);
        #pragma unroll
        for (int j = 0; j < 4; j++) {
            const int c = nbase + j * 8 + (lane & 3) * 2;
            const float bx = bias[c], by = bias[c + 1];
            const uint32_t lo = packbf(fmaxf(acc[i][j][0] + bx, 0.f),
                                       fmaxf(acc[i][j][1] + by, 0.f));
            const uint32_t hi = packbf(fmaxf(acc[i][j][2] + bx, 0.f),
                                       fmaxf(acc[i][j][3] + by, 0.f));
            *(uint32_t*)(smem + ACT_OFF + r0 * WS_BIG + c * 2)       = lo;
            *(uint32_t*)(smem + ACT_OFF + (r0 + 8) * WS_BIG + c * 2) = hi;
        }
    }
}

extern "C" __global__ void __launch_bounds__(NTH, 1)
ngp_ws_kernel(const float* __restrict__ coords,
              const float* __restrict__ emb,
              const float* __restrict__ W0, const float* __restrict__ b0,
              const float* __restrict__ W1, const float* __restrict__ b1,
              const float* __restrict__ W2, const float* __restrict__ b2,
              float* __restrict__ out, int npts)
{
    extern __shared__ char smem[];
    const uint32_t sb = smem_u32(smem);
    const int t = threadIdx.x;
    const int lane = t & 31;
    const int w = t >> 5;

    // ---- one-time weight staging (all 384 threads) ----
    for (int i = t; i < 7168; i += NTH) ((uint32_t*)(smem + W0T_OFF))[i] = 0;
    for (int i = t; i < 2112; i += NTH) ((uint32_t*)(smem + W2T_OFF))[i] = 0;
    __syncthreads();
    for (int i = t; i < 256 * 256; i += NTH) {
        const int k = i >> 8, n = i & 255;
        *(__nv_bfloat16*)(smem + W1T_OFF + n * WS_BIG + k * 2) = __float2bfloat16(W1[i]);
    }
    for (int i = t; i < 34 * 256; i += NTH) {
        const int k = i >> 8, n = i & 255;
        *(__nv_bfloat16*)(smem + W0T_OFF + n * WS_SMALL + k * 2) = __float2bfloat16(W0[i]);
    }
    for (int i = t; i < 256 * 3; i += NTH) {
        const int k = i / 3, n = i - 3 * k;
        *(__nv_bfloat16*)(smem + W2T_OFF + n * WS_BIG + k * 2) = __float2bfloat16(W2[i]);
    }
    float* b0s = (float*)(smem + B0_OFF);
    float* b1s = (float*)(smem + B1_OFF);
    float* b2s = (float*)(smem + B2_OFF);
    float* outbuf = (float*)(smem + OUTB_OFF);
    for (int i = t; i < 256; i += NTH) { b0s[i] = b0[i]; b1s[i] = b1[i]; }
    if (t < 3) b2s[t] = b2[t];
    __syncthreads();

    const int ntiles = (npts + PTS - 1) / PTS;

    if (t >= NCONS) {
        // ======================= PRODUCER: encode tiles =======================
        const int tp = t - NCONS;        // 0..127
        const int p  = tp >> 1;          // point 0..63
        const int g  = tp & 1;           // half: 8 levels each
        int iter = 0;
        for (int tile = blockIdx.x; tile < ntiles; tile += gridDim.x, iter++) {
            const int b = iter & 1;
            if (iter >= 2) bar_sync(BAR_EMPTY0 + b, NTH);

            const int gp = tile * PTS + p;
            float2 c = make_float2(0.f, 0.f);
            if (gp < npts) c = ((const float2*)coords)[gp];
            const float x = fminf(fmaxf(c.x, -1.f), 1.f);
            const float y = fminf(fmaxf(c.y, -1.f), 1.f);
            char* xrow = smem + X_OFF + b * X_BUFSZ + p * WS_SMALL;

            if (g == 0) {
                *(uint32_t*)xrow = packbf(x, y);
            } else {      // zero pad k = 34..47
                #pragma unroll
                for (int z = 0; z < 7; z++) *(uint32_t*)(xrow + 68 + 4 * z) = 0;
            }
            #pragma unroll
            for (int li = 0; li < 8; li++) {
                const int l = g * 8 + li;
                const float res  = RES_TAB[l];
                const float grid = 2.0f / res;
                const float fx = floorf((x + 1.0f) / grid);
                const float fy = floorf((y + 1.0f) / grid);
                const float wx = (x - (fx * grid - 1.0f)) / grid;
                const float wy = (y - (fy * grid - 1.0f)) / grid;
                const unsigned bx = (unsigned)(int)fx;
                const unsigned by = (unsigned)(int)fy;
                const unsigned hy0 = by * PRIME1;
                const unsigned hy1 = (by + 1u) * PRIME1;
                const float2* tabl = (const float2*)emb + (size_t)l * TABLE_SIZE;
                const float2 e00 = tabl[(bx ^ hy0) & HASH_MASK];
                const float2 e01 = tabl[(bx ^ hy1) & HASH_MASK];
                const float2 e10 = tabl[((bx + 1u) ^ hy0) & HASH_MASK];
                const float2 e11 = tabl[((bx + 1u) ^ hy1) & HASH_MASK];
                const float omx = 1.f - wx, omy = 1.f - wy;
                const float f0 = (e00.x * omx + e10.x * wx) * omy + (e01.x * omx + e11.x * wx) * wy;
                const float f1 = (e00.y * omx + e10.y * wx) * omy + (e01.y * omx + e11.y * wx) * wy;
                *(uint32_t*)(xrow + (2 + 2 * l) * 2) = packbf(f0, f1);
            }
            bar_arrive(BAR_FULL0 + b, NTH);
        }
    } else {
        // ======================= CONSUMER: 3 GEMMs ===========================
        const int arow  = (lane & 7) + ((lane >> 3) & 1) * 8;
        const int akoff = (lane >> 4) * 8;
        const int brow  = lane & 7;
        const int bkoff = ((lane >> 3) & 1) * 8;
        const int nbase = w * 32;

        const uint32_t xlane0 = sb + X_OFF   + arow * WS_SMALL + akoff * 2;
        const uint32_t alane  = sb + ACT_OFF + arow * WS_BIG   + akoff * 2;
        const uint32_t w0lane = sb + W0T_OFF + (nbase + brow) * WS_SMALL + bkoff * 2;
        const uint32_t w1lane = sb + W1T_OFF + (nbase + brow) * WS_BIG   + bkoff * 2;
        const uint32_t w2lane = sb + W2T_OFF + ((w >> 2) * 8 + brow) * WS_BIG + bkoff * 2;
        const uint32_t a2lane = alane + (w & 3) * 16 * WS_BIG;

        int iter = 0;
        for (int tile = blockIdx.x; tile < ntiles; tile += gridDim.x, iter++) {
            const int b = iter & 1;
            bar_sync(BAR_FULL0 + b, NTH);               // wait encode(tile) done

            // ---------- layer 0: [64,48] @ W0t -> relu -> ACT ----------
            {
                float acc[4][4][4];
                #pragma unroll
                for (int i = 0; i < 4; i++)
                    #pragma unroll
                    for (int j = 0; j < 4; j++)
                        #pragma unroll
                        for (int q = 0; q < 4; q++) acc[i][j][q] = 0.f;
                const uint32_t xl = xlane0 + b * X_BUFSZ;
                #pragma unroll
                for (int ks = 0; ks < 3; ks++) {
                    uint32_t a[4][4], bb[4][2];
                    #pragma unroll
                    for (int i = 0; i < 4; i++) ldm_x4(a[i], xl + i * 16 * WS_SMALL + ks * 32);
                    #pragma unroll
                    for (int j = 0; j < 4; j++) ldm_x2(bb[j], w0lane + j * 8 * WS_SMALL + ks * 32);
                    #pragma unroll
                    for (int i = 0; i < 4; i++)
                        #pragma unroll
                        for (int j = 0; j < 4; j++) mma_bf16(acc[i][j], a[i], bb[j]);
                }
                epi_store(acc, smem, b0s, nbase, lane);
            }
            bar_sync(BAR_CONS, NCONS);                  // X reads + ACT writes done
            bar_arrive(BAR_EMPTY0 + b, NTH);            // release X buffer

            // ---------- layer 1: [64,256] @ W1t -> relu -> ACT ----------
            {
                float acc[4][4][4];
                #pragma unroll
                for (int i = 0; i < 4; i++)
                    #pragma unroll
                    for (int j = 0; j < 4; j++)
                        #pragma unroll
                        for (int q = 0; q < 4; q++) acc[i][j][q] = 0.f;
                #pragma unroll
                for (int ks = 0; ks < 16; ks++) {
                    uint32_t a[4][4], bb[4][2];
                    #pragma unroll
                    for (int i = 0; i < 4; i++) ldm_x4(a[i], alane + i * 16 * WS_BIG + ks * 32);
                    #pragma unroll
                    for (int j = 0; j < 4; j++) ldm_x2(bb[j], w1lane + j * 8 * WS_BIG + ks * 32);
                    #pragma unroll
                    for (int i = 0; i < 4; i++)
                        #pragma unroll
                        for (int j = 0; j < 4; j++) mma_bf16(acc[i][j], a[i], bb[j]);
                }
                bar_sync(BAR_CONS, NCONS);              // ACT reads done before overwrite
                epi_store(acc, smem, b1s, nbase, lane);
            }
            bar_sync(BAR_CONS, NCONS);

            // ---------- layer 2 + sigmoid ----------
            {
                float acc2[4] = {0.f, 0.f, 0.f, 0.f};
                #pragma unroll 4
                for (int ks = 0; ks < 16; ks++) {
                    uint32_t a[4], bb[2];
                    ldm_x4(a, a2lane + ks * 32);
                    ldm_x2(bb, w2lane + ks * 32);
                    mma_bf16(acc2, a, bb);
                }
                if (w < 4) {
                    const int r = (w & 3) * 16 + (lane >> 2);
                    const int c = (lane & 3) * 2;
                    if (c < 3) {
                        outbuf[r * 3 + c]       = 1.f / (1.f + expf(-(acc2[0] + b2s[c])));
                        outbuf[(r + 8) * 3 + c] = 1.f / (1.f + expf(-(acc2[2] + b2s[c])));
                    }
                    if (c + 1 < 3) {
                        outbuf[r * 3 + c + 1]       = 1.f / (1.f + expf(-(acc2[1] + b2s[c + 1])));
                        outbuf[(r + 8) * 3 + c + 1] = 1.f / (1.f + expf(-(acc2[3] + b2s[c + 1])));
                    }
                }
            }
            bar_sync(BAR_CONS, NCONS);                  // outbuf ready

            if (t < PTS * 3) {
                const long gi = (long)tile * (PTS * 3) + t;
                if (gi < (long)npts * 3) out[gi] = outbuf[t];
            }
        }
    }
}

extern "C" void kernel_launch(void* const* d_in, const int* in_sizes, int n_in,
                              void* d_out, int out_size)
{
    const float* coords = (const float*)d_in[0];
    const float* emb    = (const float*)d_in[1];
    const float* W0     = (const float*)d_in[2];
    const float* b0     = (const float*)d_in[3];
    const float* W1     = (const float*)d_in[4];
    const float* b1     = (const float*)d_in[5];
    const float* W2     = (const float*)d_in[6];
    const float* b2     = (const float*)d_in[7];
    float* out          = (float*)d_out;

    const int npts = in_sizes[0] / 2;

    int dev = 0, nsm = 148;
    cudaGetDevice(&dev);
    cudaDeviceGetAttribute(&nsm, cudaDevAttrMultiProcessorCount, dev);

    cudaFuncSetAttribute(ngp_ws_kernel,
                         cudaFuncAttributeMaxDynamicSharedMemorySize, SMEM_BYTES);

    ngp_ws_kernel<<<nsm, NTH, SMEM_BYTES>>>(coords, emb, W0, b0, W1, b1, W2, b2, out, npts);
}